// round 16
// baseline (speedup 1.0000x reference)
#include <cuda_runtime.h>

// Per-node weight accumulator. Zero at module load; phase 2 re-zeroes after
// consuming, so every graph replay starts from zeros.
__device__ float g_w[4 * 1024 * 1024];
__device__ double g_acc[8];
__device__ unsigned int g_count;

// ---------------- Phase 1: per-element det(J) scattered to node weights -----
// Validated champion shape (R7/R12): grid-stride @ 2048 blocks, __ldcs index
// stream, 3 interleaved REDG per element. Adds only the PDL trigger at entry
// so the dependent phase-2 grid can begin its independent val-streaming early.
__global__ __launch_bounds__(256) void phase1_kernel(
    const float* __restrict__ coords,    // (N_NODES, 2)
    const int*   __restrict__ elements,  // (E, 3)
    int n_elements)
{
#if __CUDA_ARCH__ >= 900
    cudaTriggerProgrammaticLaunchCompletion();
#endif
    const int stride = gridDim.x * blockDim.x;
    for (int e = blockIdx.x * blockDim.x + threadIdx.x; e < n_elements; e += stride) {
        const int i0 = __ldcs(elements + 3 * e + 0);
        const int i1 = __ldcs(elements + 3 * e + 1);
        const int i2 = __ldcs(elements + 3 * e + 2);

        const float2 c0 = *reinterpret_cast<const float2*>(coords + 2 * i0);
        const float2 c1 = *reinterpret_cast<const float2*>(coords + 2 * i1);
        const float2 c2 = *reinterpret_cast<const float2*>(coords + 2 * i2);

        // det(J) for Tri3 (scale by 1/6 deferred to finalize).
        const float det = (c1.x - c0.x) * (c2.y - c0.y)
                        - (c1.y - c0.y) * (c2.x - c0.x);

        atomicAdd(&g_w[i0], det);   // REDG.F32, no return
        atomicAdd(&g_w[i1], det);
        atomicAdd(&g_w[i2], det);
    }
}

// ---------------- Phase 2: dense dot  out[v] = (1/6) sum_n w[n]*vals[n][v] ---
// PDL secondary: front-batches the phase1-independent vals4 stream BEFORE
// cudaGridDependencySynchronize(), overlapping it with phase1's tail. Only
// the w reads/zeroes wait for phase1.
static const int P2_THREADS = 128;
static const int P2_UNROLL  = 16;

__global__ __launch_bounds__(P2_THREADS) void phase2_kernel(
    const float4* __restrict__ vals4,  // 2*N_NODES float4s
    float* __restrict__ out,
    int n_f4, int nblocks)
{
    const int T = nblocks * P2_THREADS;  // even
    const int t = blockIdx.x * P2_THREADS + threadIdx.x;

    const bool exact = (n_f4 == T * P2_UNROLL);

    // ---- Pre-sync section: vals4 stream (independent of phase 1) ----
    float4 vreg[P2_UNROLL];
    if (exact) {
#pragma unroll
        for (int k = 0; k < P2_UNROLL; k++)
            vreg[k] = vals4[t + k * T];
    } else {
#pragma unroll
        for (int k = 0; k < P2_UNROLL; k++) {
            const int j = t + k * T;
            vreg[k] = (j < n_f4) ? vals4[j] : make_float4(0.f, 0.f, 0.f, 0.f);
        }
    }

    // ---- Wait for phase 1 grid completion (memory made visible) ----
#if __CUDA_ARCH__ >= 900
    cudaGridDependencySynchronize();
#endif

    // ---- Post-sync: w reads + zero for next replay ----
    float wreg[P2_UNROLL];
    if (exact) {
#pragma unroll
        for (int k = 0; k < P2_UNROLL; k++)
            wreg[k] = __ldcs(&g_w[(t + k * T) >> 1]);
        if ((t & 1) == 0) {   // even thread owns even j=2n -> every node once
#pragma unroll
            for (int k = 0; k < P2_UNROLL; k++)
                g_w[(t + k * T) >> 1] = 0.0f;
        }
    } else {
#pragma unroll
        for (int k = 0; k < P2_UNROLL; k++) {
            const int j = t + k * T;
            wreg[k] = (j < n_f4) ? __ldcs(&g_w[j >> 1]) : 0.0f;
        }
        if ((t & 1) == 0) {
#pragma unroll
            for (int k = 0; k < P2_UNROLL; k++) {
                const int j = t + k * T;
                if (j < n_f4) g_w[j >> 1] = 0.0f;
            }
        }
    }

    float4 acc = make_float4(0.f, 0.f, 0.f, 0.f);
#pragma unroll
    for (int k = 0; k < P2_UNROLL; k++) {
        acc.x += wreg[k] * vreg[k].x;
        acc.y += wreg[k] * vreg[k].y;
        acc.z += wreg[k] * vreg[k].z;
        acc.w += wreg[k] * vreg[k].w;
    }

    // Parity-preserving xor reduction (16,8,4,2): lane0 = even-lane sum
    // (v0-3), lane1 = odd-lane sum (v4-7).
#pragma unroll
    for (int off = 16; off >= 2; off >>= 1) {
        acc.x += __shfl_xor_sync(0xFFFFFFFFu, acc.x, off);
        acc.y += __shfl_xor_sync(0xFFFFFFFFu, acc.y, off);
        acc.z += __shfl_xor_sync(0xFFFFFFFFu, acc.z, off);
        acc.w += __shfl_xor_sync(0xFFFFFFFFu, acc.w, off);
    }

    __shared__ float4 sred[4][2];  // [warp][parity]
    const int warp = threadIdx.x >> 5;
    const int lane = threadIdx.x & 31;
    if (lane < 2) sred[warp][lane] = acc;
    __syncthreads();

    if (threadIdx.x < 2) {
        const int p = threadIdx.x;  // 0 -> v0-3, 1 -> v4-7
        float4 sum = make_float4(0.f, 0.f, 0.f, 0.f);
#pragma unroll
        for (int w = 0; w < 4; w++) {
            sum.x += sred[w][p].x;  sum.y += sred[w][p].y;
            sum.z += sred[w][p].z;  sum.w += sred[w][p].w;
        }
        atomicAdd(&g_acc[4 * p + 0], (double)sum.x);
        atomicAdd(&g_acc[4 * p + 1], (double)sum.y);
        atomicAdd(&g_acc[4 * p + 2], (double)sum.z);
        atomicAdd(&g_acc[4 * p + 3], (double)sum.w);
    }

    // Last-block-done: fused finalize + state reset (replay-deterministic).
    __shared__ bool is_last;
    __threadfence();
    if (threadIdx.x == 0) {
        unsigned int old = atomicInc(&g_count, (unsigned int)(nblocks - 1));
        is_last = (old == (unsigned int)(nblocks - 1));
    }
    __syncthreads();

    if (is_last && threadIdx.x < 8) {
        const double val = atomicAdd(&g_acc[threadIdx.x], 0.0);
        out[threadIdx.x] = (float)(val * (1.0 / 6.0));  // fold quad weight
        g_acc[threadIdx.x] = 0.0;
    }
}

extern "C" void kernel_launch(void* const* d_in, const int* in_sizes, int n_in,
                              void* d_out, int out_size) {
    const float* nodal_values = (const float*)d_in[0];
    const float* coords       = (const float*)d_in[1];
    const int*   elements     = (const int*)d_in[2];
    float* out = (float*)d_out;

    const int n_elements = in_sizes[2] / 3;
    const int n_nodes    = in_sizes[1] / 2;
    const int n_f4       = n_nodes * 2;

    phase1_kernel<<<2048, 256>>>(coords, elements, n_elements);

    const int p2_blocks =
        (n_f4 + P2_THREADS * P2_UNROLL - 1) / (P2_THREADS * P2_UNROLL);  // 1024

    // Launch phase 2 as a PDL secondary: it may start (and stream vals4)
    // while phase 1 is still finishing; cudaGridDependencySynchronize()
    // inside the kernel enforces the data dependency on g_w.
    cudaLaunchConfig_t cfg = {};
    cfg.gridDim  = dim3(p2_blocks, 1, 1);
    cfg.blockDim = dim3(P2_THREADS, 1, 1);
    cfg.dynamicSmemBytes = 0;
    cfg.stream = 0;
    cudaLaunchAttribute attrs[1];
    attrs[0].id = cudaLaunchAttributeProgrammaticStreamSerialization;
    attrs[0].val.programmaticStreamSerializationAllowed = 1;
    cfg.attrs = attrs;
    cfg.numAttrs = 1;

    cudaError_t err = cudaLaunchKernelEx(
        &cfg, phase2_kernel,
        reinterpret_cast<const float4*>(nodal_values), out, n_f4, p2_blocks);
    if (err != cudaSuccess) {
        // Fallback: plain serialized launch (gridsync is a no-op then).
        phase2_kernel<<<p2_blocks, P2_THREADS>>>(
            reinterpret_cast<const float4*>(nodal_values), out, n_f4, p2_blocks);
    }
}

// round 17
// speedup vs baseline: 1.0334x; 1.0334x over previous
#include <cuda_runtime.h>

// Per-node weight accumulator. Zero at module load; phase 2 re-zeroes after
// consuming, so every graph replay starts from zeros.
__device__ float g_w[4 * 1024 * 1024];
__device__ double g_acc[8];
__device__ unsigned int g_count;

// ---------------- Phase 1: per-element det(J) scattered to node weights -----
// Grid-stride, 3 interleaved REDG per element. Plain loads on the element
// stream: 24 MB of indices stays L2-resident across graph replays (total
// working set 68 MB < 126 MB L2), so replays hit L2 instead of DRAM.
__global__ __launch_bounds__(256) void phase1_kernel(
    const float* __restrict__ coords,    // (N_NODES, 2)
    const int*   __restrict__ elements,  // (E, 3)
    int n_elements)
{
    const int stride = gridDim.x * blockDim.x;
    for (int e = blockIdx.x * blockDim.x + threadIdx.x; e < n_elements; e += stride) {
        const int i0 = elements[3 * e + 0];
        const int i1 = elements[3 * e + 1];
        const int i2 = elements[3 * e + 2];

        const float2 c0 = *reinterpret_cast<const float2*>(coords + 2 * i0);
        const float2 c1 = *reinterpret_cast<const float2*>(coords + 2 * i1);
        const float2 c2 = *reinterpret_cast<const float2*>(coords + 2 * i2);

        // det(J) for Tri3 (scale by 1/6 deferred to finalize).
        const float det = (c1.x - c0.x) * (c2.y - c0.y)
                        - (c1.y - c0.y) * (c2.x - c0.x);

        atomicAdd(&g_w[i0], det);   // REDG.F32, no return
        atomicAdd(&g_w[i1], det);
        atomicAdd(&g_w[i2], det);
    }
}

// ---------------- Phase 2: dense dot  out[v] = (1/6) sum_n w[n]*vals[n][v] ---
// nodal_values viewed as 2*N float4s. Even float4 j -> v0..3 of node j/2,
// odd j -> v4..7. Thread parity == j parity (T even), so each thread always
// accumulates the same 4-value group; xor-reduce preserves parity.
// 128-thread blocks, unroll 16: 32 front-batched loads per thread.
static const int P2_THREADS = 128;
static const int P2_UNROLL  = 16;

__global__ __launch_bounds__(P2_THREADS) void phase2_kernel(
    const float4* __restrict__ vals4,  // 2*N_NODES float4s
    float* __restrict__ out,
    int n_f4, int nblocks)
{
    const int T = nblocks * P2_THREADS;  // even
    const int t = blockIdx.x * P2_THREADS + threadIdx.x;

    // Front-batched guarded loads: up to 32 independent loads in flight.
    // g_w uses __ldcs (consumed once per replay, then rewritten - evict-first
    // is free); vals4 uses default policy to stay L2-resident across replays.
    float  wreg[P2_UNROLL];
    float4 vreg[P2_UNROLL];
#pragma unroll
    for (int k = 0; k < P2_UNROLL; k++) {
        const int j = t + k * T;
        if (j < n_f4) {
            wreg[k] = __ldcs(&g_w[j >> 1]);
            vreg[k] = vals4[j];
        } else {
            wreg[k] = 0.0f;
            vreg[k] = make_float4(0.f, 0.f, 0.f, 0.f);
        }
    }

    // Zero w for next replay: even threads own even j = 2n -> every node once.
    if ((t & 1) == 0) {
#pragma unroll
        for (int k = 0; k < P2_UNROLL; k++) {
            const int j = t + k * T;
            if (j < n_f4) g_w[j >> 1] = 0.0f;
        }
    }

    float4 acc = make_float4(0.f, 0.f, 0.f, 0.f);
#pragma unroll
    for (int k = 0; k < P2_UNROLL; k++) {
        acc.x += wreg[k] * vreg[k].x;
        acc.y += wreg[k] * vreg[k].y;
        acc.z += wreg[k] * vreg[k].z;
        acc.w += wreg[k] * vreg[k].w;
    }

    // Parity-preserving xor reduction (16,8,4,2): lane0 = even-lane sum
    // (v0-3), lane1 = odd-lane sum (v4-7).
#pragma unroll
    for (int off = 16; off >= 2; off >>= 1) {
        acc.x += __shfl_xor_sync(0xFFFFFFFFu, acc.x, off);
        acc.y += __shfl_xor_sync(0xFFFFFFFFu, acc.y, off);
        acc.z += __shfl_xor_sync(0xFFFFFFFFu, acc.z, off);
        acc.w += __shfl_xor_sync(0xFFFFFFFFu, acc.w, off);
    }

    __shared__ float4 sred[4][2];  // [warp][parity]
    const int warp = threadIdx.x >> 5;
    const int lane = threadIdx.x & 31;
    if (lane < 2) sred[warp][lane] = acc;
    __syncthreads();

    if (threadIdx.x < 2) {
        const int p = threadIdx.x;  // 0 -> v0-3, 1 -> v4-7
        float4 sum = make_float4(0.f, 0.f, 0.f, 0.f);
#pragma unroll
        for (int w = 0; w < 4; w++) {
            sum.x += sred[w][p].x;  sum.y += sred[w][p].y;
            sum.z += sred[w][p].z;  sum.w += sred[w][p].w;
        }
        atomicAdd(&g_acc[4 * p + 0], (double)sum.x);
        atomicAdd(&g_acc[4 * p + 1], (double)sum.y);
        atomicAdd(&g_acc[4 * p + 2], (double)sum.z);
        atomicAdd(&g_acc[4 * p + 3], (double)sum.w);
    }

    // Last-block-done: fused finalize + state reset (replay-deterministic).
    __shared__ bool is_last;
    __threadfence();
    if (threadIdx.x == 0) {
        unsigned int old = atomicInc(&g_count, (unsigned int)(nblocks - 1));
        is_last = (old == (unsigned int)(nblocks - 1));
    }
    __syncthreads();

    if (is_last && threadIdx.x < 8) {
        const double val = atomicAdd(&g_acc[threadIdx.x], 0.0);
        out[threadIdx.x] = (float)(val * (1.0 / 6.0));  // fold quad weight
        g_acc[threadIdx.x] = 0.0;
    }
}

extern "C" void kernel_launch(void* const* d_in, const int* in_sizes, int n_in,
                              void* d_out, int out_size) {
    const float* nodal_values = (const float*)d_in[0];
    const float* coords       = (const float*)d_in[1];
    const int*   elements     = (const int*)d_in[2];
    float* out = (float*)d_out;

    const int n_elements = in_sizes[2] / 3;
    const int n_nodes    = in_sizes[1] / 2;
    const int n_f4       = n_nodes * 2;

    phase1_kernel<<<3072, 256>>>(coords, elements, n_elements);

    const int p2_blocks =
        (n_f4 + P2_THREADS * P2_UNROLL - 1) / (P2_THREADS * P2_UNROLL);  // 977
    phase2_kernel<<<p2_blocks, P2_THREADS>>>(
        reinterpret_cast<const float4*>(nodal_values), out, n_f4, p2_blocks);
}